// round 10
// baseline (speedup 1.0000x reference)
#include <cuda_runtime.h>
#include <cuda_bf16.h>
#include <cstdint>
#include <cstddef>

#define LL 32
#define HH 128
#define KD 130
#define KPE 152           // padded row elements (304 B = 19*16B, odd -> conflict-free)
#define HALFE 72          // K elements per half (144 B, 9 x 16B)
#define SPB 2
#define NBLK 256
#define NTHR 256
#define NCELL 1024
#define EPSF 1e-8f
#define W_BYTES  (HH * KPE * 2u)   // 38912
#define SM_BYTES 512u
#define TX_BYTES (W_BYTES + 2u * SM_BYTES)

typedef unsigned long long ull;

__device__ unsigned short g_Wb[(size_t)NCELL * HH * KPE];  // bf16, padded rows
__device__ float2 g_pre[NBLK][NCELL];                      // deferred pre-activations

struct __align__(16) Smem {
    unsigned short W[2][HH * KPE];  // 77824
    float bvec[2][HH];              //  1024
    float wfvec[2][HH];             //  1024
    uint32_t hv[LL][HH];            // 16384  bf16x2 (h0,h1)
    float2 inp[2][KPE];             //  2432  ([k] = (s0,s1)); k>=130 stays 0
    float2 red2[HH];                //  1024  half1 partials
    float2 red3[2][4];              //    64  per-warp head partials
    uint32_t sbits[SPB][LL];        //   256
    ull mbar[2];                    //    16
};                                  // 100048 B -> 2 CTAs/SM

__device__ __forceinline__ uint32_t s2u(const void* p) {
    return (uint32_t)__cvta_generic_to_shared(p);
}
__device__ __forceinline__ void mbar_init(uint32_t a, uint32_t c) {
    asm volatile("mbarrier.init.shared::cta.b64 [%0], %1;" :: "r"(a), "r"(c) : "memory");
}
__device__ __forceinline__ void mbar_expect(uint32_t a, uint32_t tx) {
    asm volatile("mbarrier.arrive.expect_tx.shared::cta.b64 _, [%0], %1;" :: "r"(a), "r"(tx) : "memory");
}
__device__ __forceinline__ void tma1d(uint32_t dst, const void* src, uint32_t bytes, uint32_t mbar) {
    asm volatile("cp.async.bulk.shared::cluster.global.mbarrier::complete_tx::bytes [%0], [%1], %2, [%3];"
                 :: "r"(dst), "l"(src), "r"(bytes), "r"(mbar) : "memory");
}
__device__ __forceinline__ void mbar_wait(uint32_t a, uint32_t ph) {
    uint32_t done = 0;
    while (!done) {
        asm volatile("{\n\t.reg .pred p;\n\t"
                     "mbarrier.try_wait.parity.acquire.cta.shared::cta.b64 p, [%1], %2;\n\t"
                     "selp.b32 %0, 1, 0, p;\n\t}"
                     : "=r"(done) : "r"(a), "r"(ph) : "memory");
    }
}
__device__ __forceinline__ float tanh_fast(float x) {
    float y; asm("tanh.approx.f32 %0, %1;" : "=f"(y) : "f"(x)); return y;
}
__device__ __forceinline__ float bflo(uint32_t u) { return __uint_as_float(u << 16); }
__device__ __forceinline__ float bfhi(uint32_t u) { return __uint_as_float(u & 0xffff0000u); }
__device__ __forceinline__ uint32_t packbf2(float a, float b) {
    uint32_t r; asm("cvt.rn.bf16x2.f32 %0, %2, %1;" : "=r"(r) : "f"(a), "f"(b)); return r;
}

// ---- prep: fp32 W -> bf16, rows 130 -> 152 ----
__global__ void prep_kernel(const float* __restrict__ gW) {
    const int c = blockIdx.x;
    const float* src = gW + (size_t)c * (HH * KD);
    unsigned short* dst = g_Wb + (size_t)c * (HH * KPE);
    for (int t = threadIdx.x; t < HH * KPE; t += blockDim.x) {
        const int row = t / KPE, col = t - row * KPE;
        __nv_bfloat16 b = __float2bfloat16((col < KD) ? src[row * KD + col] : 0.f);
        dst[t] = *reinterpret_cast<unsigned short*>(&b);
    }
}

// ---- main persistent kernel: 2 samples/CTA, 2 CTAs/SM, warp-split-K ----
__global__ void __launch_bounds__(NTHR, 2)
rnn2d_kernel(const float* __restrict__ gS, const float* __restrict__ gB,
             const float* __restrict__ gWf, const float* __restrict__ gBf,
             float* __restrict__ out)
{
    extern __shared__ unsigned char smem_raw[];
    Smem& s = *reinterpret_cast<Smem*>(smem_raw);
    const int tid = threadIdx.x;
    const int blk = blockIdx.x;
    const int n = tid & 127;         // neuron
    const int half = tid >> 7;       // K-half
    const int lid = tid & 31, wid = tid >> 5;

    // ---- init ----
    const float* gs = gS + (size_t)blk * SPB * NCELL;
    if (tid < SPB * LL) {
        const int sm = tid >> 5, row = tid & 31;
        const float* rp = gs + sm * NCELL + row * LL;
        uint32_t bits = 0;
        #pragma unroll
        for (int j = 0; j < LL; ++j) bits |= (rp[j] > 0.5f ? 1u : 0u) << j;
        s.sbits[sm][row] = bits;
    }
    for (int t = tid; t < LL * HH; t += NTHR) ((uint32_t*)s.hv)[t] = 0u;
    for (int t = tid; t < 2 * KPE; t += NTHR) ((float2*)s.inp)[t] = make_float2(0.f, 0.f);
    __syncthreads();
    if (tid == 0) s.inp[0][1] = make_float2(2.f, 2.f);

    const uint32_t mb0 = s2u(&s.mbar[0]);
    const uint32_t mb1 = s2u(&s.mbar[1]);
    if (tid == 0) {
        mbar_init(mb0, 1);
        mbar_init(mb1, 1);
        asm volatile("fence.mbarrier_init.release.cluster;" ::: "memory");
        mbar_expect(mb0, TX_BYTES);
        tma1d(s2u(&s.W[0][0]),     g_Wb, W_BYTES,  mb0);
        tma1d(s2u(&s.bvec[0][0]),  gB,   SM_BYTES, mb0);
        tma1d(s2u(&s.wfvec[0][0]), gWf,  SM_BYTES, mb0);
    }
    __syncthreads();

    for (int c = 0; c < NCELL; ++c) {
        const int buf = c & 1;
        const int r = c >> 5, j = c & 31;
        const int col = (r & 1) ? (LL - 1 - j) : j;

        if (tid == 0 && c + 1 < NCELL) {
            const int cn = c + 1, rn = cn >> 5, jn = cn & 31;
            const int coln = (rn & 1) ? (LL - 1 - jn) : jn;
            const int celln = (rn << 5) + coln;
            const uint32_t mb = buf ? mb0 : mb1;
            mbar_expect(mb, TX_BYTES);
            tma1d(s2u(&s.W[buf ^ 1][0]),     g_Wb + (size_t)celln * HH * KPE, W_BYTES,  mb);
            tma1d(s2u(&s.bvec[buf ^ 1][0]),  gB  + celln * HH,                SM_BYTES, mb);
            tma1d(s2u(&s.wfvec[buf ^ 1][0]), gWf + celln * HH,                SM_BYTES, mb);
        }
        // deferred PRE store for previous cell (warp 4, off the critical path)
        if (tid == 128 && c > 0) {
            const int pc = c - 1, pr = pc >> 5, pj = pc & 31;
            const int pcol = (pr & 1) ? (LL - 1 - pj) : pj;
            const float2 q0 = s.red3[pc & 1][0], q1 = s.red3[pc & 1][1];
            const float2 q2 = s.red3[pc & 1][2], q3 = s.red3[pc & 1][3];
            g_pre[blk][(pr << 5) + pcol] =
                make_float2(q0.x + q1.x + q2.x + q3.x, q0.y + q1.y + q2.y + q3.y);
        }
        mbar_wait(buf ? mb1 : mb0, (c >> 1) & 1);

        // ---- phase 1: half-matvec (all 256 threads) ----
        const unsigned char* wb = (const unsigned char*)&s.W[buf][0] + n * 304 + half * 144;
        const float4* ip4 = (const float4*)&s.inp[buf][half * HALFE];
        float a0 = 0.f, a1 = 0.f, b0 = 0.f, b1 = 0.f;
        #pragma unroll
        for (int i = 0; i < 9; ++i) {
            const uint4 wp = *(const uint4*)(wb + i * 16);
            const float4 q0 = ip4[i * 4 + 0];
            const float4 q1 = ip4[i * 4 + 1];
            const float4 q2 = ip4[i * 4 + 2];
            const float4 q3 = ip4[i * 4 + 3];
            float w;
            w = bflo(wp.x); a0 += w * q0.x; b0 += w * q0.y;
            w = bfhi(wp.x); a1 += w * q0.z; b1 += w * q0.w;
            w = bflo(wp.y); a0 += w * q1.x; b0 += w * q1.y;
            w = bfhi(wp.y); a1 += w * q1.z; b1 += w * q1.w;
            w = bflo(wp.z); a0 += w * q2.x; b0 += w * q2.y;
            w = bfhi(wp.z); a1 += w * q2.z; b1 += w * q2.w;
            w = bflo(wp.w); a0 += w * q3.x; b0 += w * q3.y;
            w = bfhi(wp.w); a1 += w * q3.z; b1 += w * q3.w;
        }
        const float2 part = make_float2(a0 + a1, b0 + b1);
        if (half) s.red2[n] = part;
        __syncthreads();   // BAR1

        // ---- phase 2: combine + activate + build next input (half 0 only) ----
        if (half == 0) {
            const float2 oth = s.red2[n];
            const float bi2 = 2.f * s.bvec[buf][n];
            const float h0 = tanh_fast(part.x + oth.x + bi2);
            const float h1 = tanh_fast(part.y + oth.y + bi2);

            const float wfi = s.wfvec[buf][n];
            float p0 = wfi * h0, p1 = wfi * h1;
            #pragma unroll
            for (int o = 16; o; o >>= 1) {
                p0 += __shfl_xor_sync(0xffffffffu, p0, o);
                p1 += __shfl_xor_sync(0xffffffffu, p1, o);
            }
            if (lid == 0) s.red3[c & 1][wid] = make_float2(p0, p1);

            s.hv[col][n] = packbf2(h0, h1);
            if (c + 1 < NCELL) {
                const int cn = c + 1, rn = cn >> 5, jn = cn & 31;
                const int coln = (rn & 1) ? (LL - 1 - jn) : jn;
                float2 v = make_float2(h0, h1);
                if (jn != 0) {
                    const uint32_t t = s.hv[coln][n];
                    v = make_float2(h0 + bflo(t), h1 + bfhi(t));
                }
                s.inp[buf ^ 1][2 + n] = v;
                if (tid == 0) {
                    float2 e0, e1;
                    #pragma unroll
                    for (int si = 0; si < SPB; ++si) {
                        const float xh = (jn == 0) ? 0.f : (float)((s.sbits[si][rn] >> col) & 1u);
                        const float xv = (rn == 0) ? 0.f : (float)((s.sbits[si][rn - 1] >> coln) & 1u);
                        ((float*)&e0)[si] = xh + xv;
                        ((float*)&e1)[si] = 2.f - xh - xv;
                    }
                    s.inp[buf ^ 1][0] = e0;
                    s.inp[buf ^ 1][1] = e1;
                }
            }
        }
        __syncthreads();   // BAR2
    }

    // store last cell's PRE
    if (tid == 128) {
        const int pc = NCELL - 1, pr = pc >> 5, pj = pc & 31;
        const int pcol = (pr & 1) ? (LL - 1 - pj) : pj;
        const float2 q0 = s.red3[pc & 1][0], q1 = s.red3[pc & 1][1];
        const float2 q2 = s.red3[pc & 1][2], q3 = s.red3[pc & 1][3];
        g_pre[blk][(pr << 5) + pcol] =
            make_float2(q0.x + q1.x + q2.x + q3.x, q0.y + q1.y + q2.y + q3.y);
    }
    __syncthreads();

    // ---- bulk log-prob ----
    float lp0 = 0.f, lp1 = 0.f;
    for (int c = tid; c < NCELL; c += NTHR) {
        const float bfv = __ldg(gBf + c);
        const float2 pr = g_pre[blk][c];
        const int row = c >> 5, bit = c & 31;
        float z, xh, m;
        z = pr.x + bfv; xh = 1.f / (1.f + __expf(-z));
        m = (float)((s.sbits[0][row] >> bit) & 1u);
        lp0 += m * __logf(xh + EPSF) + (1.f - m) * __logf(1.f - xh + EPSF);
        z = pr.y + bfv; xh = 1.f / (1.f + __expf(-z));
        m = (float)((s.sbits[1][row] >> bit) & 1u);
        lp1 += m * __logf(xh + EPSF) + (1.f - m) * __logf(1.f - xh + EPSF);
    }
    #pragma unroll
    for (int o = 16; o; o >>= 1) {
        lp0 += __shfl_xor_sync(0xffffffffu, lp0, o);
        lp1 += __shfl_xor_sync(0xffffffffu, lp1, o);
    }
    if (lid == 0) s.red2[wid] = make_float2(lp0, lp1);
    __syncthreads();
    if (tid < SPB) {
        float acc = 0.f;
        #pragma unroll
        for (int w = 0; w < 8; ++w) acc += ((float*)&s.red2[w])[tid];
        out[blk * SPB + tid] = acc;
    }
}

extern "C" void kernel_launch(void* const* d_in, const int* in_sizes, int n_in,
                              void* d_out, int out_size) {
    const float* samples = (const float*)d_in[0];
    const float* W1      = (const float*)d_in[1];
    const float* b1      = (const float*)d_in[2];
    const float* Wf      = (const float*)d_in[3];
    const float* bf      = (const float*)d_in[4];
    float* out = (float*)d_out;

    prep_kernel<<<NCELL, 256>>>(W1);

    const size_t smem = sizeof(Smem);
    cudaFuncSetAttribute(rnn2d_kernel, cudaFuncAttributeMaxDynamicSharedMemorySize, (int)smem);
    rnn2d_kernel<<<NBLK, NTHR, smem>>>(samples, b1, Wf, bf, out);
}